// round 2
// baseline (speedup 1.0000x reference)
#include <cuda_runtime.h>
#include <cuda_bf16.h>

// Problem constants
#define N_NODES   100000
#define N_EDGES   1600000
#define E_TOT     (N_EDGES + N_NODES)   // with self-loops
#define N_FEAT    128
#define N_CLASSES 10
#define N_GRAPHS  256

// ---------------- device scratch (no allocs allowed) ----------------
// NOTE: indices (edge_index, batch) are int32 — JAX x64 is disabled so the
// reference's "int64" tensors are silently int32.
__device__ __align__(16) float d_h1 [N_NODES * 64];     // layer1 features [N,8,8]
__device__ __align__(16) float d_als1[N_NODES * 8];
__device__ __align__(16) float d_ald1[N_NODES * 8];
__device__ __align__(16) float d_s1 [N_NODES * 8];
__device__ __align__(16) float d_out1[N_NODES * 64];
__device__ __align__(16) float d_h2 [N_NODES * 128];
__device__ __align__(16) float d_als2[N_NODES];
__device__ __align__(16) float d_ald2[N_NODES];
__device__ __align__(16) float d_s2 [N_NODES];
__device__ __align__(16) float d_out2[N_NODES * 128];

__device__ __forceinline__ float lrelu(float v) { return v > 0.f ? v : 0.2f * v; }

// ---------------- zero accumulators ----------------
__global__ void kzero() {
    int tid = blockIdx.x * blockDim.x + threadIdx.x;
    int stride = gridDim.x * blockDim.x;
    float4 z = make_float4(0.f, 0.f, 0.f, 0.f);
    float4* p;
    p = (float4*)d_s1;   for (int i = tid; i < N_NODES * 8 / 4;   i += stride) p[i] = z;
    p = (float4*)d_out1; for (int i = tid; i < N_NODES * 64 / 4;  i += stride) p[i] = z;
    p = (float4*)d_s2;   for (int i = tid; i < N_NODES / 4;       i += stride) p[i] = z;
    p = (float4*)d_out2; for (int i = tid; i < N_NODES * 128 / 4; i += stride) p[i] = z;
}

// ---------------- K1: h1 = x @ W1  (100000x128 @ 128x64) ----------------
#define NPB1 32
__global__ __launch_bounds__(256) void k1_gemm(const float* __restrict__ x,
                                               const float* __restrict__ W1) {
    __shared__ float Ws[128 * 64];
    __shared__ float xs[NPB1 * 128];
    int t  = threadIdx.x;
    int nb = blockIdx.x * NPB1;
    for (int i = t; i < 128 * 64; i += 256) Ws[i] = W1[i];
    for (int i = t; i < NPB1 * 128; i += 256) {
        int nl = i >> 7, k = i & 127;
        int n = nb + nl;
        xs[i] = (n < N_NODES) ? x[n * 128 + k] : 0.f;
    }
    __syncthreads();
    int o = t & 63;
    int nl0 = t >> 6;  // 0..3
    float acc[8];
#pragma unroll
    for (int r = 0; r < 8; r++) acc[r] = 0.f;
    for (int k = 0; k < 128; k++) {
        float w = Ws[k * 64 + o];
#pragma unroll
        for (int r = 0; r < 8; r++)
            acc[r] += xs[(nl0 + r * 4) * 128 + k] * w;
    }
#pragma unroll
    for (int r = 0; r < 8; r++) {
        int n = nb + nl0 + r * 4;
        if (n < N_NODES) d_h1[n * 64 + o] = acc[r];
    }
}

// ---------------- K1b: attention logits per (node, head) ----------------
__global__ void k1b_al(const float* __restrict__ a_src1,
                       const float* __restrict__ a_dst1) {
    int gid = blockIdx.x * blockDim.x + threadIdx.x;
    if (gid >= N_NODES * 8) return;
    int n = gid >> 3, h = gid & 7;
    float s = 0.f, d = 0.f;
#pragma unroll
    for (int c = 0; c < 8; c++) {
        float v = d_h1[n * 64 + h * 8 + c];
        s += v * a_src1[h * 8 + c];
        d += v * a_dst1[h * 8 + c];
    }
    d_als1[gid] = s;
    d_ald1[gid] = d;
}

// ---------------- K2: layer1 softmax denominators ----------------
__global__ void k2_denom(const int* __restrict__ ei) {
    int e = blockIdx.x * blockDim.x + threadIdx.x;
    if (e >= E_TOT) return;
    int src, dst;
    if (e < N_EDGES) { src = ei[e]; dst = ei[N_EDGES + e]; }
    else             { src = dst = e - N_EDGES; }
    const float4* as = (const float4*)(d_als1 + src * 8);
    const float4* ad = (const float4*)(d_ald1 + dst * 8);
    float4 s0 = as[0], s1 = as[1], dd0 = ad[0], dd1 = ad[1];
    float4 e0, e1;
    e0.x = expf(lrelu(s0.x + dd0.x)); e0.y = expf(lrelu(s0.y + dd0.y));
    e0.z = expf(lrelu(s0.z + dd0.z)); e0.w = expf(lrelu(s0.w + dd0.w));
    e1.x = expf(lrelu(s1.x + dd1.x)); e1.y = expf(lrelu(s1.y + dd1.y));
    e1.z = expf(lrelu(s1.z + dd1.z)); e1.w = expf(lrelu(s1.w + dd1.w));
    atomicAdd((float4*)(d_s1 + dst * 8), e0);
    atomicAdd((float4*)(d_s1 + dst * 8) + 1, e1);
}

// ---------------- K3: layer1 aggregation (4 threads / edge, 2 heads each) ----------------
__global__ void k3_agg(const int* __restrict__ ei) {
    long long gid = blockIdx.x * (long long)blockDim.x + threadIdx.x;
    int e = (int)(gid >> 2);
    int lane = (int)(gid & 3);
    if (e >= E_TOT) return;
    int src, dst;
    if (e < N_EDGES) { src = ei[e]; dst = ei[N_EDGES + e]; }
    else             { src = dst = e - N_EDGES; }
    float2 as = *(const float2*)(d_als1 + src * 8 + lane * 2);
    float2 ad = *(const float2*)(d_ald1 + dst * 8 + lane * 2);
    float2 sv = *(const float2*)(d_s1   + dst * 8 + lane * 2);
    float a0 = expf(lrelu(as.x + ad.x)) / (sv.x + 1e-16f);
    float a1 = expf(lrelu(as.y + ad.y)) / (sv.y + 1e-16f);
    const float4* hs = (const float4*)(d_h1 + src * 64 + lane * 16);
    float4* od = (float4*)(d_out1 + dst * 64 + lane * 16);
    float4 h0 = hs[0], h1v = hs[1], h2v = hs[2], h3v = hs[3];
    float4 v;
    v.x = h0.x * a0; v.y = h0.y * a0; v.z = h0.z * a0; v.w = h0.w * a0; atomicAdd(od + 0, v);
    v.x = h1v.x * a0; v.y = h1v.y * a0; v.z = h1v.z * a0; v.w = h1v.w * a0; atomicAdd(od + 1, v);
    v.x = h2v.x * a1; v.y = h2v.y * a1; v.z = h2v.z * a1; v.w = h2v.w * a1; atomicAdd(od + 2, v);
    v.x = h3v.x * a1; v.y = h3v.y * a1; v.z = h3v.z * a1; v.w = h3v.w * a1; atomicAdd(od + 3, v);
}

// ---------------- K5: h2 = relu(out1 + b1) @ W2  (100000x64 @ 64x128) ----------------
#define NPB2 32
__global__ __launch_bounds__(256) void k5_gemm(const float* __restrict__ W2,
                                               const float* __restrict__ b1) {
    __shared__ float Ws[64 * 128];
    __shared__ float xs[NPB2 * 64];
    int t  = threadIdx.x;
    int nb = blockIdx.x * NPB2;
    for (int i = t; i < 64 * 128; i += 256) Ws[i] = W2[i];
    for (int i = t; i < NPB2 * 64; i += 256) {
        int nl = i >> 6, k = i & 63;
        int n = nb + nl;
        float v = 0.f;
        if (n < N_NODES) {
            v = d_out1[n * 64 + k] + b1[k];
            v = v > 0.f ? v : 0.f;
        }
        xs[i] = v;
    }
    __syncthreads();
    int o = t & 127;
    int nl0 = t >> 7;  // 0..1
    float acc[16];
#pragma unroll
    for (int r = 0; r < 16; r++) acc[r] = 0.f;
    for (int k = 0; k < 64; k++) {
        float w = Ws[k * 128 + o];
#pragma unroll
        for (int r = 0; r < 16; r++)
            acc[r] += xs[(nl0 + r * 2) * 64 + k] * w;
    }
#pragma unroll
    for (int r = 0; r < 16; r++) {
        int n = nb + nl0 + r * 2;
        if (n < N_NODES) d_h2[n * 128 + o] = acc[r];
    }
}

// ---------------- K5b: layer2 attention logits ----------------
__global__ void k5b_al(const float* __restrict__ a_src2,
                       const float* __restrict__ a_dst2) {
    int n = blockIdx.x * blockDim.x + threadIdx.x;
    if (n >= N_NODES) return;
    float s = 0.f, d = 0.f;
    const float4* hr = (const float4*)(d_h2 + n * 128);
    const float4* asv = (const float4*)a_src2;
    const float4* adv = (const float4*)a_dst2;
#pragma unroll 8
    for (int k = 0; k < 32; k++) {
        float4 h = hr[k], a = asv[k], b = adv[k];
        s += h.x * a.x + h.y * a.y + h.z * a.z + h.w * a.w;
        d += h.x * b.x + h.y * b.y + h.z * b.z + h.w * b.w;
    }
    d_als2[n] = s;
    d_ald2[n] = d;
}

// ---------------- K6: layer2 softmax denominators ----------------
__global__ void k6_denom(const int* __restrict__ ei) {
    int e = blockIdx.x * blockDim.x + threadIdx.x;
    if (e >= E_TOT) return;
    int src, dst;
    if (e < N_EDGES) { src = ei[e]; dst = ei[N_EDGES + e]; }
    else             { src = dst = e - N_EDGES; }
    float ex = expf(lrelu(d_als2[src] + d_ald2[dst]));
    atomicAdd(&d_s2[dst], ex);
}

// ---------------- K7: layer2 aggregation (8 threads / edge) ----------------
__global__ void k7_agg(const int* __restrict__ ei) {
    long long gid = blockIdx.x * (long long)blockDim.x + threadIdx.x;
    int e = (int)(gid >> 3);
    int lane = (int)(gid & 7);
    if (e >= E_TOT) return;
    int src, dst;
    if (e < N_EDGES) { src = ei[e]; dst = ei[N_EDGES + e]; }
    else             { src = dst = e - N_EDGES; }
    float alpha = expf(lrelu(d_als2[src] + d_ald2[dst])) / (d_s2[dst] + 1e-16f);
    const float4* hs = (const float4*)(d_h2 + src * 128 + lane * 16);
    float4* od = (float4*)(d_out2 + dst * 128 + lane * 16);
#pragma unroll
    for (int j = 0; j < 4; j++) {
        float4 h = hs[j];
        float4 v;
        v.x = h.x * alpha; v.y = h.y * alpha; v.z = h.z * alpha; v.w = h.w * alpha;
        atomicAdd(od + j, v);
    }
}

// ---------------- K8: pool + FC + log_softmax (one block per graph) ----------------
__global__ __launch_bounds__(128) void k8_pool(const int* __restrict__ batch,
                                               const float* __restrict__ b2,
                                               const float* __restrict__ fc_w,
                                               const float* __restrict__ fc_b,
                                               float* __restrict__ out) {
    int g = blockIdx.x;
    int t = threadIdx.x;
    int lo, hi;
    {
        int a = 0, b = N_NODES;
        while (a < b) { int m = (a + b) >> 1; if (batch[m] < g) a = m + 1; else b = m; }
        lo = a;
        a = lo; b = N_NODES;
        while (a < b) { int m = (a + b) >> 1; if (batch[m] < g + 1) a = m + 1; else b = m; }
        hi = a;
    }
    int cnt = hi - lo;
    float acc = 0.f;
    for (int n = lo; n < hi; n++) acc += d_out2[n * 128 + t];
    float inv = 1.f / (float)max(cnt, 1);
    __shared__ float sp[128];
    sp[t] = (acc + (float)cnt * b2[t]) * inv;
    __syncthreads();
    __shared__ float sl[N_CLASSES];
    if (t < N_CLASSES) {
        float v = fc_b[t];
        for (int k = 0; k < 128; k++) v += sp[k] * fc_w[k * N_CLASSES + t];
        sl[t] = v;
    }
    __syncthreads();
    __shared__ float s_m, s_lse;
    if (t == 0) {
        float m = sl[0];
        for (int c = 1; c < N_CLASSES; c++) m = fmaxf(m, sl[c]);
        float se = 0.f;
        for (int c = 0; c < N_CLASSES; c++) se += expf(sl[c] - m);
        s_m = m;
        s_lse = logf(se);
    }
    __syncthreads();
    if (t < N_CLASSES) out[g * N_CLASSES + t] = sl[t] - s_m - s_lse;
}

// ---------------- launch ----------------
extern "C" void kernel_launch(void* const* d_in, const int* in_sizes, int n_in,
                              void* d_out, int out_size) {
    const float* x      = (const float*)d_in[0];
    const int*   ei     = (const int*)d_in[1];
    const int*   batch  = (const int*)d_in[2];
    const float* W1     = (const float*)d_in[3];
    const float* a_src1 = (const float*)d_in[4];
    const float* a_dst1 = (const float*)d_in[5];
    const float* b1     = (const float*)d_in[6];
    const float* W2     = (const float*)d_in[7];
    const float* a_src2 = (const float*)d_in[8];
    const float* a_dst2 = (const float*)d_in[9];
    const float* b2     = (const float*)d_in[10];
    const float* fc_w   = (const float*)d_in[11];
    const float* fc_b   = (const float*)d_in[12];
    float* out = (float*)d_out;

    kzero<<<1024, 256>>>();
    k1_gemm<<<(N_NODES + NPB1 - 1) / NPB1, 256>>>(x, W1);
    k1b_al<<<(N_NODES * 8 + 255) / 256, 256>>>(a_src1, a_dst1);
    k2_denom<<<(E_TOT + 255) / 256, 256>>>(ei);
    k3_agg<<<(int)(((long long)E_TOT * 4 + 255) / 256), 256>>>(ei);
    k5_gemm<<<(N_NODES + NPB2 - 1) / NPB2, 256>>>(W2, b1);
    k5b_al<<<(N_NODES + 255) / 256, 256>>>(a_src2, a_dst2);
    k6_denom<<<(E_TOT + 255) / 256, 256>>>(ei);
    k7_agg<<<(int)(((long long)E_TOT * 8 + 255) / 256), 256>>>(ei);
    k8_pool<<<N_GRAPHS, 128>>>(batch, b2, fc_w, fc_b, out);
}

// round 3
// speedup vs baseline: 2.4438x; 2.4438x over previous
#include <cuda_runtime.h>
#include <cuda_bf16.h>

// Problem constants
#define N_NODES   100000
#define N_EDGES   1600000
#define E_TOT     (N_EDGES + N_NODES)   // with self-loops
#define N_FEAT    128
#define N_CLASSES 10
#define N_GRAPHS  256

#define SCAN_B    512
#define NB_SCAN   ((N_NODES + SCAN_B - 1) / SCAN_B)   // 196

// ---------------- device scratch ----------------
__device__ __align__(16) float d_h1 [N_NODES * 64];
__device__ __align__(16) float d_als1[N_NODES * 8];
__device__ __align__(16) float d_ald1[N_NODES * 8];
__device__ __align__(16) float d_out1[N_NODES * 64];
__device__ __align__(16) float d_h2 [N_NODES * 128];
__device__ __align__(16) float d_als2[N_NODES];
__device__ __align__(16) float d_ald2[N_NODES];
__device__ __align__(16) float d_out2[N_NODES * 128];

// CSR scratch
__device__ int d_deg   [N_NODES];
__device__ int d_incl  [N_NODES];
__device__ int d_bsum  [256];
__device__ int d_bofs  [256];
__device__ int d_rowptr[N_NODES + 1];
__device__ int d_wofs  [N_NODES];
__device__ int d_esrc  [E_TOT];

__device__ __forceinline__ float lrelu(float v) { return v > 0.f ? v : 0.2f * v; }

// ================= CSR build =================
__global__ void k_zero_deg() {
    int i = blockIdx.x * SCAN_B + threadIdx.x;
    if (i < N_NODES) d_deg[i] = 0;
}

__global__ void k_hist(const int* __restrict__ ei) {
    int e = blockIdx.x * 256 + threadIdx.x;
    if (e >= E_TOT) return;
    int dst = (e < N_EDGES) ? ei[N_EDGES + e] : (e - N_EDGES);
    atomicAdd(&d_deg[dst], 1);
}

__global__ __launch_bounds__(SCAN_B) void k_scan1() {
    __shared__ int s[SCAN_B];
    int i = blockIdx.x * SCAN_B + threadIdx.x;
    int v = (i < N_NODES) ? d_deg[i] : 0;
    s[threadIdx.x] = v;
    __syncthreads();
#pragma unroll
    for (int off = 1; off < SCAN_B; off <<= 1) {
        int t = (threadIdx.x >= off) ? s[threadIdx.x - off] : 0;
        __syncthreads();
        s[threadIdx.x] += t;
        __syncthreads();
    }
    if (i < N_NODES) d_incl[i] = s[threadIdx.x];
    if (threadIdx.x == SCAN_B - 1) d_bsum[blockIdx.x] = s[SCAN_B - 1];
}

__global__ __launch_bounds__(256) void k_scan2() {
    __shared__ int s[256];
    int t = threadIdx.x;
    int v = (t < NB_SCAN) ? d_bsum[t] : 0;
    s[t] = v;
    __syncthreads();
#pragma unroll
    for (int off = 1; off < 256; off <<= 1) {
        int u = (t >= off) ? s[t - off] : 0;
        __syncthreads();
        s[t] += u;
        __syncthreads();
    }
    if (t < NB_SCAN) d_bofs[t] = s[t] - v;   // exclusive
}

__global__ __launch_bounds__(SCAN_B) void k_scan3() {
    int i = blockIdx.x * SCAN_B + threadIdx.x;
    if (i < N_NODES) d_rowptr[i + 1] = d_incl[i] + d_bofs[blockIdx.x];
    if (i == 0) d_rowptr[0] = 0;
}

__global__ void k_copyw() {
    int i = blockIdx.x * SCAN_B + threadIdx.x;
    if (i < N_NODES) d_wofs[i] = d_rowptr[i];
}

__global__ void k_scatter(const int* __restrict__ ei) {
    int e = blockIdx.x * 256 + threadIdx.x;
    if (e >= E_TOT) return;
    int src, dst;
    if (e < N_EDGES) { src = ei[e]; dst = ei[N_EDGES + e]; }
    else             { src = dst = e - N_EDGES; }
    int pos = atomicAdd(&d_wofs[dst], 1);
    d_esrc[pos] = src;
}

// ================= K1: h1 = x @ W1 (100000x128 @ 128x64) =================
#define NPB1 32
__global__ __launch_bounds__(256) void k1_gemm(const float* __restrict__ x,
                                               const float* __restrict__ W1) {
    __shared__ float Ws[128 * 64];
    __shared__ float xs[NPB1 * 128];
    int t  = threadIdx.x;
    int nb = blockIdx.x * NPB1;
    for (int i = t; i < 128 * 64; i += 256) Ws[i] = W1[i];
    for (int i = t; i < NPB1 * 128; i += 256) {
        int nl = i >> 7, k = i & 127;
        int n = nb + nl;
        xs[i] = (n < N_NODES) ? x[n * 128 + k] : 0.f;
    }
    __syncthreads();
    int o = t & 63;
    int nl0 = t >> 6;
    float acc[8];
#pragma unroll
    for (int r = 0; r < 8; r++) acc[r] = 0.f;
    for (int k = 0; k < 128; k++) {
        float w = Ws[k * 64 + o];
#pragma unroll
        for (int r = 0; r < 8; r++)
            acc[r] += xs[(nl0 + r * 4) * 128 + k] * w;
    }
#pragma unroll
    for (int r = 0; r < 8; r++) {
        int n = nb + nl0 + r * 4;
        if (n < N_NODES) d_h1[n * 64 + o] = acc[r];
    }
}

// ================= K1b: layer1 attention logits =================
__global__ void k1b_al(const float* __restrict__ a_src1,
                       const float* __restrict__ a_dst1) {
    int gid = blockIdx.x * blockDim.x + threadIdx.x;
    if (gid >= N_NODES * 8) return;
    int n = gid >> 3, h = gid & 7;
    float s = 0.f, d = 0.f;
#pragma unroll
    for (int c = 0; c < 8; c++) {
        float v = d_h1[n * 64 + h * 8 + c];
        s += v * a_src1[h * 8 + c];
        d += v * a_dst1[h * 8 + c];
    }
    d_als1[gid] = s;
    d_ald1[gid] = d;
}

// ================= L1 aggregation: warp per dst node =================
// 8 heads x 8 ch. Fused softmax (denominator in regs) + aggregate + bias + relu.
__global__ __launch_bounds__(256) void l1_agg(const float* __restrict__ b1) {
    int gw   = (blockIdx.x * 256 + threadIdx.x) >> 5;
    int lane = threadIdx.x & 31;
    if (gw >= N_NODES) return;
    int dst = gw;
    int beg = d_rowptr[dst], end = d_rowptr[dst + 1];
    int h8 = lane & 7;
    float ald_h = d_ald1[dst * 8 + h8];

    // pass 1: denominator (4 edges in flight; lanes 0-7 per edge cover heads)
    float sum = 0.f;
    for (int i = beg + (lane >> 3); i < end; i += 4) {
        int src = d_esrc[i];
        sum += expf(lrelu(d_als1[src * 8 + h8] + ald_h));
    }
    sum += __shfl_xor_sync(0xffffffffu, sum, 8);
    sum += __shfl_xor_sync(0xffffffffu, sum, 16);
    float inv = 1.f / (sum + 1e-16f);

    // pass 2: aggregate. lane owns cols [2*lane, 2*lane+1], head = lane>>2
    int myhead = lane >> 2;
    float inv_my = __shfl_sync(0xffffffffu, inv, myhead);
    float acc0 = 0.f, acc1 = 0.f;
#pragma unroll 2
    for (int i = beg; i < end; i++) {
        int src = d_esrc[i];
        float e_h = expf(lrelu(d_als1[src * 8 + h8] + ald_h));
        float alpha = __shfl_sync(0xffffffffu, e_h, myhead) * inv_my;
        float2 hv = *(const float2*)(d_h1 + src * 64 + lane * 2);
        acc0 += hv.x * alpha;
        acc1 += hv.y * alpha;
    }
    float r0 = acc0 + b1[lane * 2];
    float r1 = acc1 + b1[lane * 2 + 1];
    r0 = r0 > 0.f ? r0 : 0.f;
    r1 = r1 > 0.f ? r1 : 0.f;
    *(float2*)(d_out1 + dst * 64 + lane * 2) = make_float2(r0, r1);
}

// ================= K5: h2 = out1 @ W2 (100000x64 @ 64x128) =================
#define NPB2 32
__global__ __launch_bounds__(256) void k5_gemm(const float* __restrict__ W2) {
    __shared__ float Ws[64 * 128];
    __shared__ float xs[NPB2 * 64];
    int t  = threadIdx.x;
    int nb = blockIdx.x * NPB2;
    for (int i = t; i < 64 * 128; i += 256) Ws[i] = W2[i];
    for (int i = t; i < NPB2 * 64; i += 256) {
        int nl = i >> 6, k = i & 63;
        int n = nb + nl;
        xs[i] = (n < N_NODES) ? d_out1[n * 64 + k] : 0.f;
    }
    __syncthreads();
    int o = t & 127;
    int nl0 = t >> 7;
    float acc[16];
#pragma unroll
    for (int r = 0; r < 16; r++) acc[r] = 0.f;
    for (int k = 0; k < 64; k++) {
        float w = Ws[k * 128 + o];
#pragma unroll
        for (int r = 0; r < 16; r++)
            acc[r] += xs[(nl0 + r * 2) * 64 + k] * w;
    }
#pragma unroll
    for (int r = 0; r < 16; r++) {
        int n = nb + nl0 + r * 2;
        if (n < N_NODES) d_h2[n * 128 + o] = acc[r];
    }
}

// ================= K5b: layer2 attention logits =================
__global__ void k5b_al(const float* __restrict__ a_src2,
                       const float* __restrict__ a_dst2) {
    int n = blockIdx.x * blockDim.x + threadIdx.x;
    if (n >= N_NODES) return;
    float s = 0.f, d = 0.f;
    const float4* hr  = (const float4*)(d_h2 + n * 128);
    const float4* asv = (const float4*)a_src2;
    const float4* adv = (const float4*)a_dst2;
#pragma unroll 8
    for (int k = 0; k < 32; k++) {
        float4 h = hr[k], a = asv[k], b = adv[k];
        s += h.x * a.x + h.y * a.y + h.z * a.z + h.w * a.w;
        d += h.x * b.x + h.y * b.y + h.z * b.z + h.w * b.w;
    }
    d_als2[n] = s;
    d_ald2[n] = d;
}

// ================= L2 aggregation: warp per dst node (1 head, 128 ch) =================
__global__ __launch_bounds__(256) void l2_agg() {
    int gw   = (blockIdx.x * 256 + threadIdx.x) >> 5;
    int lane = threadIdx.x & 31;
    if (gw >= N_NODES) return;
    int dst = gw;
    int beg = d_rowptr[dst], end = d_rowptr[dst + 1];
    float ald = d_ald2[dst];

    // pass 1: denominator, 32 edges in flight
    float sum = 0.f;
    for (int i = beg + lane; i < end; i += 32)
        sum += expf(lrelu(d_als2[d_esrc[i]] + ald));
#pragma unroll
    for (int o = 16; o; o >>= 1) sum += __shfl_xor_sync(0xffffffffu, sum, o);
    float inv = 1.f / (sum + 1e-16f);

    // pass 2: aggregate. lane owns cols [4*lane, 4*lane+3]
    float4 acc = make_float4(0.f, 0.f, 0.f, 0.f);
#pragma unroll 2
    for (int i = beg; i < end; i++) {
        int src = d_esrc[i];
        float alpha = expf(lrelu(d_als2[src] + ald)) * inv;
        float4 h = *(const float4*)(d_h2 + src * 128 + lane * 4);
        acc.x += h.x * alpha;
        acc.y += h.y * alpha;
        acc.z += h.z * alpha;
        acc.w += h.w * alpha;
    }
    *(float4*)(d_out2 + dst * 128 + lane * 4) = acc;
}

// ================= K8: pool + FC + log_softmax =================
__global__ __launch_bounds__(128) void k8_pool(const int* __restrict__ batch,
                                               const float* __restrict__ b2,
                                               const float* __restrict__ fc_w,
                                               const float* __restrict__ fc_b,
                                               float* __restrict__ out) {
    int g = blockIdx.x;
    int t = threadIdx.x;
    int lo, hi;
    {
        int a = 0, b = N_NODES;
        while (a < b) { int m = (a + b) >> 1; if (batch[m] < g) a = m + 1; else b = m; }
        lo = a;
        a = lo; b = N_NODES;
        while (a < b) { int m = (a + b) >> 1; if (batch[m] < g + 1) a = m + 1; else b = m; }
        hi = a;
    }
    int cnt = hi - lo;
    float acc = 0.f;
    for (int n = lo; n < hi; n++) acc += d_out2[n * 128 + t];
    float inv = 1.f / (float)max(cnt, 1);
    __shared__ float sp[128];
    sp[t] = (acc + (float)cnt * b2[t]) * inv;
    __syncthreads();
    __shared__ float sl[N_CLASSES];
    if (t < N_CLASSES) {
        float v = fc_b[t];
        for (int k = 0; k < 128; k++) v += sp[k] * fc_w[k * N_CLASSES + t];
        sl[t] = v;
    }
    __syncthreads();
    __shared__ float s_m, s_lse;
    if (t == 0) {
        float m = sl[0];
        for (int c = 1; c < N_CLASSES; c++) m = fmaxf(m, sl[c]);
        float se = 0.f;
        for (int c = 0; c < N_CLASSES; c++) se += expf(sl[c] - m);
        s_m = m;
        s_lse = logf(se);
    }
    __syncthreads();
    if (t < N_CLASSES) out[g * N_CLASSES + t] = sl[t] - s_m - s_lse;
}

// ================= launch =================
extern "C" void kernel_launch(void* const* d_in, const int* in_sizes, int n_in,
                              void* d_out, int out_size) {
    const float* x      = (const float*)d_in[0];
    const int*   ei     = (const int*)d_in[1];
    const int*   batch  = (const int*)d_in[2];
    const float* W1     = (const float*)d_in[3];
    const float* a_src1 = (const float*)d_in[4];
    const float* a_dst1 = (const float*)d_in[5];
    const float* b1     = (const float*)d_in[6];
    const float* W2     = (const float*)d_in[7];
    const float* a_src2 = (const float*)d_in[8];
    const float* a_dst2 = (const float*)d_in[9];
    const float* b2     = (const float*)d_in[10];
    const float* fc_w   = (const float*)d_in[11];
    const float* fc_b   = (const float*)d_in[12];
    float* out = (float*)d_out;

    const int EB = (E_TOT + 255) / 256;
    const int WB = (N_NODES * 32 + 255) / 256;   // warp-per-node kernels

    // CSR build
    k_zero_deg<<<NB_SCAN, SCAN_B>>>();
    k_hist<<<EB, 256>>>(ei);
    k_scan1<<<NB_SCAN, SCAN_B>>>();
    k_scan2<<<1, 256>>>();
    k_scan3<<<NB_SCAN, SCAN_B>>>();
    k_copyw<<<NB_SCAN, SCAN_B>>>();
    k_scatter<<<EB, 256>>>(ei);

    // layer 1
    k1_gemm<<<(N_NODES + NPB1 - 1) / NPB1, 256>>>(x, W1);
    k1b_al<<<(N_NODES * 8 + 255) / 256, 256>>>(a_src1, a_dst1);
    l1_agg<<<WB, 256>>>(b1);

    // layer 2
    k5_gemm<<<(N_NODES + NPB2 - 1) / NPB2, 256>>>(W2);
    k5b_al<<<(N_NODES + 255) / 256, 256>>>(a_src2, a_dst2);
    l2_agg<<<WB, 256>>>();

    // readout
    k8_pool<<<N_GRAPHS, 128>>>(batch, b2, fc_w, fc_b, out);
}